// round 3
// baseline (speedup 1.0000x reference)
#include <cuda_runtime.h>
#include <math.h>

#define Bn 16
#define Qn 64
#define Mn 512
#define Fn 16
#define Dn 512
#define INF_ 1e20f

// d_out layout: [new_query (B,Q,D)][in_mem (B,M,D)][out_mem (B,M,D)]
#define OFF_NQ 0
#define OFF_IN (Bn*Qn*Dn)                 // 524288
#define OFF_OM (OFF_IN + Bn*Mn*Dn)       // 4718592

typedef unsigned long long ull;

// ---------------- scratch (no allocations allowed) ----------------
__device__ float g_att[Bn*Qn*Mn];   // att_qm (B,Q,M)  2MB
__device__ float g_rmax[Bn*Qn];
__device__ float g_rsum[Bn*Qn];
__device__ float g_cmax[Bn*Mn];
__device__ float g_csum[Bn*Mn];

// packed fp32x2 FMA (only reachable via PTX; doubles fp32 FMA rate on sm_103a)
#define FMA2(c, a, b) asm("fma.rn.f32x2 %0, %1, %2, %0;" : "+l"(c) : "l"(a), "l"(b))

// =====================================================================
// K1: attention = query @ in_memory^T, masks, max over F -> g_att
// Block: 64 q x 128 rows (8 m * 16 f). 256 threads, 8x4 f32x2 acc each.
// =====================================================================
__global__ __launch_bounds__(256, 2) void k1_attention(
    const float* __restrict__ query, const float* __restrict__ inmem,
    const float* __restrict__ cmask, const float* __restrict__ qmask)
{
    const int b  = blockIdx.y;
    const int m0 = blockIdx.x * 8;     // 8 m per block
    const int r0 = m0 * 16;            // 128 rows

    __shared__ __align__(16) ull As2[16][66];    // [k2][q]  (k-pairs packed)
    __shared__ __align__(16) ull Bs2[16][130];   // [k2][r]
    __shared__ float cmS[128];
    __shared__ float qmS[64];

    const int tid = threadIdx.x;
    const int tx  = tid & 31;          // -> rows  r = tx*4 .. tx*4+3
    const int ty  = tid >> 5;          // -> q     q = ty*8 .. ty*8+7

    const float* Qb = query + (size_t)b * Qn * Dn;
    const float* Xb = inmem + ((size_t)b * (Mn*Fn) + r0) * Dn;

    if (tid < 128) cmS[tid] = cmask[(size_t)(b*Mn + m0)*Fn + tid];
    if (tid < 64)  qmS[tid] = qmask[b*Qn + tid];

    ull acc[8][4];
    #pragma unroll
    for (int i = 0; i < 8; ++i)
        #pragma unroll
        for (int j = 0; j < 4; ++j) acc[i][j] = 0ULL;

    const int qq  = tid >> 3;          // 0..31 (row-ish index for loads)
    const int kk  = (tid & 7) << 2;    // 0,4,...,28
    const int k2s = kk >> 1;

    for (int kc = 0; kc < Dn; kc += 32) {
        // load A (query) 64x32, transposed into k-pair-major packs
        #pragma unroll
        for (int p = 0; p < 2; ++p) {
            float4 v = *(const float4*)(Qb + (size_t)(qq + p*32)*Dn + kc + kk);
            *(float2*)&As2[k2s  ][qq + p*32] = make_float2(v.x, v.y);
            *(float2*)&As2[k2s+1][qq + p*32] = make_float2(v.z, v.w);
        }
        // load B (in_memory rows) 128x32
        #pragma unroll
        for (int p = 0; p < 4; ++p) {
            float4 v = *(const float4*)(Xb + (size_t)(qq + p*32)*Dn + kc + kk);
            *(float2*)&Bs2[k2s  ][qq + p*32] = make_float2(v.x, v.y);
            *(float2*)&Bs2[k2s+1][qq + p*32] = make_float2(v.z, v.w);
        }
        __syncthreads();

        #pragma unroll
        for (int k2 = 0; k2 < 16; ++k2) {
            ull a2[8], b2[4];
            ulonglong2 t;
            t = *(const ulonglong2*)&As2[k2][ty*8+0]; a2[0]=t.x; a2[1]=t.y;
            t = *(const ulonglong2*)&As2[k2][ty*8+2]; a2[2]=t.x; a2[3]=t.y;
            t = *(const ulonglong2*)&As2[k2][ty*8+4]; a2[4]=t.x; a2[5]=t.y;
            t = *(const ulonglong2*)&As2[k2][ty*8+6]; a2[6]=t.x; a2[7]=t.y;
            t = *(const ulonglong2*)&Bs2[k2][tx*4+0]; b2[0]=t.x; b2[1]=t.y;
            t = *(const ulonglong2*)&Bs2[k2][tx*4+2]; b2[2]=t.x; b2[3]=t.y;
            #pragma unroll
            for (int i = 0; i < 8; ++i)
                #pragma unroll
                for (int j = 0; j < 4; ++j)
                    FMA2(acc[i][j], a2[i], b2[j]);
        }
        __syncthreads();
    }

    // epilogue: combine pair-lanes, apply masks, max over F (4 regs x 4 lanes)
    #pragma unroll
    for (int i = 0; i < 8; ++i) {
        const int q = ty*8 + i;
        const float qm = qmS[q];
        float mx = -3e38f;
        #pragma unroll
        for (int j = 0; j < 4; ++j) {
            const int r = tx*4 + j;
            const unsigned lo = (unsigned)(acc[i][j] & 0xffffffffULL);
            const unsigned hi = (unsigned)(acc[i][j] >> 32);
            float s = __uint_as_float(lo) + __uint_as_float(hi);
            const float cm = cmS[r];
            s = cm*s - (1.f - cm)*INF_;
            s = qm*s - (1.f - qm)*INF_;
            mx = fmaxf(mx, s);
        }
        mx = fmaxf(mx, __shfl_xor_sync(0xffffffffu, mx, 1));
        mx = fmaxf(mx, __shfl_xor_sync(0xffffffffu, mx, 2));
        if ((tx & 3) == 0)
            g_att[((size_t)(b*Qn + q))*Mn + m0 + (tx >> 2)] = mx;
    }
}

// =====================================================================
// K2: out_mem = sum_f out_memory ; in_mem_base = softmax_f(mask) . in_memory
// one block per (b,m); 128 threads, one float4 of D each
// =====================================================================
__global__ void k2_reduce(const float* __restrict__ inmem,
                          const float* __restrict__ outmem,
                          const float* __restrict__ cmask,
                          float* __restrict__ dout)
{
    const int bm = blockIdx.x;                     // 0..B*M-1
    const float* cm = cmask + (size_t)bm * Fn;

    float w[Fn];
    float mx = -3e38f;
    #pragma unroll
    for (int f = 0; f < Fn; ++f) {
        const float c = cm[f];
        const float mv = c - (1.f - c)*INF_;
        w[f] = mv; mx = fmaxf(mx, mv);
    }
    float s = 0.f;
    #pragma unroll
    for (int f = 0; f < Fn; ++f) { w[f] = __expf(w[f] - mx); s += w[f]; }
    const float inv = 1.f / s;

    const float4* X = (const float4*)(inmem  + (size_t)bm*Fn*Dn);
    const float4* Y = (const float4*)(outmem + (size_t)bm*Fn*Dn);
    const int d4 = threadIdx.x;                    // 0..127
    float4 ai = make_float4(0.f,0.f,0.f,0.f);
    float4 ao = make_float4(0.f,0.f,0.f,0.f);
    #pragma unroll
    for (int f = 0; f < Fn; ++f) {
        const float4 x = X[f*128 + d4];
        ai.x += w[f]*x.x; ai.y += w[f]*x.y; ai.z += w[f]*x.z; ai.w += w[f]*x.w;
        const float4 y = Y[f*128 + d4];
        ao.x += y.x; ao.y += y.y; ao.z += y.z; ao.w += y.w;
    }
    ai.x *= inv; ai.y *= inv; ai.z *= inv; ai.w *= inv;
    ((float4*)(dout + OFF_IN))[(size_t)bm*128 + d4] = ai;
    ((float4*)(dout + OFF_OM))[(size_t)bm*128 + d4] = ao;
}

// =====================================================================
// K3a: softmax stats over M per (b,q)
// =====================================================================
__global__ void k3a_stats()
{
    const int bq  = blockIdx.x;                    // 0..B*Q-1
    const int tid = threadIdx.x;                   // 128
    const float4 v = ((const float4*)(g_att + (size_t)bq*Mn))[tid];
    float mx = fmaxf(fmaxf(v.x, v.y), fmaxf(v.z, v.w));
    #pragma unroll
    for (int o = 16; o > 0; o >>= 1) mx = fmaxf(mx, __shfl_xor_sync(~0u, mx, o));
    __shared__ float sm[4], ss[4];
    if ((tid & 31) == 0) sm[tid >> 5] = mx;
    __syncthreads();
    mx = fmaxf(fmaxf(sm[0], sm[1]), fmaxf(sm[2], sm[3]));
    float s = __expf(v.x-mx) + __expf(v.y-mx) + __expf(v.z-mx) + __expf(v.w-mx);
    #pragma unroll
    for (int o = 16; o > 0; o >>= 1) s += __shfl_xor_sync(~0u, s, o);
    if ((tid & 31) == 0) ss[tid >> 5] = s;
    __syncthreads();
    if (tid == 0) { g_rmax[bq] = mx; g_rsum[bq] = ss[0]+ss[1]+ss[2]+ss[3]; }
}

// =====================================================================
// K3b: new_query = query + softmax_M(att) @ out_mem
// block: (64 q x 64 d) tile; 256 thr, 4x4 each; K over M in 64 chunks
// =====================================================================
__global__ __launch_bounds__(256) void k3b_newq(const float* __restrict__ query,
                                                float* __restrict__ dout)
{
    const int b  = blockIdx.y;
    const int d0 = blockIdx.x * 64;
    __shared__ __align__(16) float ps[64][68];     // [q][m_local]
    __shared__ __align__(16) float om[64][68];     // [m_local][d_local]
    const int tid = threadIdx.x;
    const int tx  = tid & 15, ty = tid >> 4;
    const int lq  = tid >> 2, sub = tid & 3;

    const float rm   = g_rmax[b*Qn + lq];
    const float rinv = 1.f / g_rsum[b*Qn + lq];
    const float* om_g = dout + OFF_OM + (size_t)b*Mn*Dn;

    float c[4][4];
    #pragma unroll
    for (int i = 0; i < 4; ++i)
        #pragma unroll
        for (int j = 0; j < 4; ++j) c[i][j] = 0.f;

    for (int mc = 0; mc < Mn; mc += 64) {
        #pragma unroll
        for (int p = 0; p < 4; ++p) {
            const int ml = sub*4 + p*16;
            float4 v = *(const float4*)(g_att + ((size_t)(b*Qn + lq))*Mn + mc + ml);
            ps[lq][ml+0] = __expf(v.x - rm)*rinv;
            ps[lq][ml+1] = __expf(v.y - rm)*rinv;
            ps[lq][ml+2] = __expf(v.z - rm)*rinv;
            ps[lq][ml+3] = __expf(v.w - rm)*rinv;
            float4 u = *(const float4*)(om_g + (size_t)(mc + lq)*Dn + d0 + ml);
            om[lq][ml+0] = u.x; om[lq][ml+1] = u.y; om[lq][ml+2] = u.z; om[lq][ml+3] = u.w;
        }
        __syncthreads();
        #pragma unroll
        for (int k = 0; k < 64; ++k) {
            const float a0 = ps[ty*4+0][k], a1 = ps[ty*4+1][k];
            const float a2 = ps[ty*4+2][k], a3 = ps[ty*4+3][k];
            const float4 bv = *(const float4*)&om[k][tx*4];
            c[0][0]+=a0*bv.x; c[0][1]+=a0*bv.y; c[0][2]+=a0*bv.z; c[0][3]+=a0*bv.w;
            c[1][0]+=a1*bv.x; c[1][1]+=a1*bv.y; c[1][2]+=a1*bv.z; c[1][3]+=a1*bv.w;
            c[2][0]+=a2*bv.x; c[2][1]+=a2*bv.y; c[2][2]+=a2*bv.z; c[2][3]+=a2*bv.w;
            c[3][0]+=a3*bv.x; c[3][1]+=a3*bv.y; c[3][2]+=a3*bv.z; c[3][3]+=a3*bv.w;
        }
        __syncthreads();
    }
    #pragma unroll
    for (int i = 0; i < 4; ++i) {
        const int q = ty*4 + i;
        const float4 qv = *(const float4*)(query + ((size_t)(b*Qn + q))*Dn + d0 + tx*4);
        float4 o = make_float4(qv.x + c[i][0], qv.y + c[i][1],
                               qv.z + c[i][2], qv.w + c[i][3]);
        *(float4*)(dout + OFF_NQ + ((size_t)(b*Qn + q))*Dn + d0 + tx*4) = o;
    }
}

// =====================================================================
// K4a: softmax stats over Q (axis=1) per (b,m)
// grid = Bn*4 blocks of 128 threads (m-chunks of 128)
// =====================================================================
__global__ void k4a_stats()
{
    const int b = blockIdx.x >> 2;
    const int m = (blockIdx.x & 3) * 128 + threadIdx.x;
    const float* base = g_att + (size_t)b*Qn*Mn + m;
    float mx = -3e38f;
    #pragma unroll 8
    for (int q = 0; q < Qn; ++q) mx = fmaxf(mx, base[q*Mn]);
    float s = 0.f;
    #pragma unroll 8
    for (int q = 0; q < Qn; ++q) s += __expf(base[q*Mn] - mx);
    g_cmax[b*Mn + m] = mx;
    g_csum[b*Mn + m] = s;
}

// =====================================================================
// K4b: in_mem += softmax_Q(att)^T @ new_query   (K = 64 q)
// block: (64 m x 64 d) tile
// =====================================================================
__global__ __launch_bounds__(256) void k4b_inmem(float* __restrict__ dout)
{
    const int b  = blockIdx.z;
    const int m0 = blockIdx.y * 64;
    const int d0 = blockIdx.x * 64;
    __shared__ __align__(16) float pt[64][68];     // [q][m_local]
    __shared__ __align__(16) float nq[64][68];     // [q][d_local]
    __shared__ float cmx[64], cs[64];
    const int tid = threadIdx.x;
    const int tx  = tid & 15, ty = tid >> 4;
    const int lq  = tid >> 2, sub = tid & 3;

    if (tid < 64) {
        cmx[tid] = g_cmax[b*Mn + m0 + tid];
        cs[tid]  = 1.f / g_csum[b*Mn + m0 + tid];
    }
    __syncthreads();

    #pragma unroll
    for (int p = 0; p < 4; ++p) {
        const int ml = sub*4 + p*16;
        float4 v = *(const float4*)(g_att + ((size_t)(b*Qn + lq))*Mn + m0 + ml);
        pt[lq][ml+0] = __expf(v.x - cmx[ml+0]) * cs[ml+0];
        pt[lq][ml+1] = __expf(v.y - cmx[ml+1]) * cs[ml+1];
        pt[lq][ml+2] = __expf(v.z - cmx[ml+2]) * cs[ml+2];
        pt[lq][ml+3] = __expf(v.w - cmx[ml+3]) * cs[ml+3];
        float4 u = *(const float4*)(dout + OFF_NQ + ((size_t)(b*Qn + lq))*Dn + d0 + ml);
        nq[lq][ml+0] = u.x; nq[lq][ml+1] = u.y; nq[lq][ml+2] = u.z; nq[lq][ml+3] = u.w;
    }
    __syncthreads();

    float c[4][4];
    #pragma unroll
    for (int i = 0; i < 4; ++i)
        #pragma unroll
        for (int j = 0; j < 4; ++j) c[i][j] = 0.f;

    #pragma unroll
    for (int k = 0; k < 64; ++k) {
        const float a0 = pt[k][ty*4+0], a1 = pt[k][ty*4+1];
        const float a2 = pt[k][ty*4+2], a3 = pt[k][ty*4+3];
        const float4 bv = *(const float4*)&nq[k][tx*4];
        c[0][0]+=a0*bv.x; c[0][1]+=a0*bv.y; c[0][2]+=a0*bv.z; c[0][3]+=a0*bv.w;
        c[1][0]+=a1*bv.x; c[1][1]+=a1*bv.y; c[1][2]+=a1*bv.z; c[1][3]+=a1*bv.w;
        c[2][0]+=a2*bv.x; c[2][1]+=a2*bv.y; c[2][2]+=a2*bv.z; c[2][3]+=a2*bv.w;
        c[3][0]+=a3*bv.x; c[3][1]+=a3*bv.y; c[3][2]+=a3*bv.z; c[3][3]+=a3*bv.w;
    }

    #pragma unroll
    for (int i = 0; i < 4; ++i) {
        const int m = m0 + ty*4 + i;
        float* p = dout + OFF_IN + ((size_t)(b*Mn + m))*Dn + d0 + tx*4;
        float4 v = *(const float4*)p;
        v.x += c[i][0]; v.y += c[i][1]; v.z += c[i][2]; v.w += c[i][3];
        *(float4*)p = v;
    }
}

// =====================================================================
extern "C" void kernel_launch(void* const* d_in, const int* in_sizes, int n_in,
                              void* d_out, int out_size)
{
    const float* query  = (const float*)d_in[0];
    const float* inmem  = (const float*)d_in[1];
    const float* outmem = (const float*)d_in[2];
    const float* cmask  = (const float*)d_in[3];
    const float* qmask  = (const float*)d_in[4];
    float* dout = (float*)d_out;
    (void)in_sizes; (void)n_in; (void)out_size;

    dim3 g1(Mn/8, Bn);
    k1_attention<<<g1, 256>>>(query, inmem, cmask, qmask);
    k2_reduce<<<Bn*Mn, 128>>>(inmem, outmem, cmask, dout);
    k3a_stats<<<Bn*Qn, 128>>>();
    dim3 g3(Dn/64, Bn);
    k3b_newq<<<g3, 256>>>(query, dout);
    k4a_stats<<<Bn*4, 128>>>();
    dim3 g4(Dn/64, Mn/64, Bn);
    k4b_inmem<<<g4, 256>>>(dout);
}

// round 4
// speedup vs baseline: 1.0498x; 1.0498x over previous
#include <cuda_runtime.h>
#include <math.h>

#define Bn 16
#define Qn 64
#define Mn 512
#define Fn 16
#define Dn 512
#define INF_ 1e20f

// d_out layout: [new_query (B,Q,D)][in_mem (B,M,D)][out_mem (B,M,D)]
#define OFF_NQ 0
#define OFF_IN (Bn*Qn*Dn)                 // 524288
#define OFF_OM (OFF_IN + Bn*Mn*Dn)       // 4718592

typedef unsigned long long ull;

// ---------------- scratch (no allocations allowed) ----------------
__device__ float g_att[Bn*Qn*Mn];   // att_qm (B,Q,M)  2MB
__device__ float g_rmax[Bn*Qn];
__device__ float g_rsum[Bn*Qn];
__device__ float g_cmax[Bn*Mn];
__device__ float g_csum[Bn*Mn];

// packed fp32x2 FMA (only reachable via PTX; doubles fp32 FMA rate on sm_103a)
#define FMA2(c, a, b) asm("fma.rn.f32x2 %0, %1, %2, %0;" : "+l"(c) : "l"(a), "l"(b))

// =====================================================================
// K1: attention = query @ in_memory^T, masks, max over F -> g_att
//     PLUS fused: in_mem_base = softmax_f(mask) . in_memory -> dout[OFF_IN]
// Block: 64 q x 128 rows (8 m * 16 f). 256 threads, 8x4 f32x2 acc each.
// =====================================================================
__global__ __launch_bounds__(256, 2) void k1_attention(
    const float* __restrict__ query, const float* __restrict__ inmem,
    const float* __restrict__ cmask, const float* __restrict__ qmask,
    float* __restrict__ dout)
{
    const int b  = blockIdx.y;
    const int m0 = blockIdx.x * 8;     // 8 m per block
    const int r0 = m0 * 16;            // 128 rows

    __shared__ __align__(16) ull As2[16][66];    // [k2][q]  (k-pairs packed)
    __shared__ __align__(16) ull Bs2[16][130];   // [k2][r]
    __shared__ float cmS[128];
    __shared__ float qmS[64];
    __shared__ float wS[8][16];                  // softmax_f weights per m

    const int tid = threadIdx.x;
    const int tx  = tid & 31;          // -> rows  r = tx*4 .. tx*4+3
    const int ty  = tid >> 5;          // -> q     q = ty*8 .. ty*8+7

    const float* Qb = query + (size_t)b * Qn * Dn;
    const float* Xb = inmem + ((size_t)b * (Mn*Fn) + r0) * Dn;

    if (tid < 128) cmS[tid] = cmask[(size_t)(b*Mn + m0)*Fn + tid];
    if (tid < 64)  qmS[tid] = qmask[b*Qn + tid];

    // per-m softmax over F of mask values: warp w handles m0+w, lanes 0..15 = f
    {
        const int wm = ty;             // warp id = m index 0..7
        const int wf = tx;
        float mv = -3e38f;
        float c = 0.f;
        if (wf < Fn) {
            c  = cmask[(size_t)(b*Mn + m0 + wm)*Fn + wf];
            mv = c - (1.f - c)*INF_;
        }
        float mx = mv;
        #pragma unroll
        for (int o = 8; o > 0; o >>= 1) mx = fmaxf(mx, __shfl_xor_sync(~0u, mx, o));
        mx = __shfl_sync(~0u, mx, 0, 16);   // lanes 16-31 irrelevant
        float e = (wf < Fn) ? __expf(mv - mx) : 0.f;
        float s = e;
        #pragma unroll
        for (int o = 8; o > 0; o >>= 1) s += __shfl_xor_sync(~0u, s, o);
        s = __shfl_sync(~0u, s, 0, 16);
        if (wf < Fn) wS[wm][wf] = e / s;
    }

    ull acc[8][4];
    #pragma unroll
    for (int i = 0; i < 8; ++i)
        #pragma unroll
        for (int j = 0; j < 4; ++j) acc[i][j] = 0ULL;

    const int qq  = tid >> 3;          // 0..31 (row-ish index for loads)
    const int kk  = (tid & 7) << 2;    // 0,4,...,28
    const int k2s = kk >> 1;

    // f-reduction work assignment: one (m,k) pair per thread
    const int rm    = tid >> 5;        // m 0..7
    const int rk    = tid & 31;        // k 0..31 within chunk
    const int rk2   = rk >> 1;
    const int rhalf = rk & 1;
    float* inout = dout + OFF_IN + ((size_t)(b*Mn + m0 + rm))*Dn + rk;

    for (int kc = 0; kc < Dn; kc += 32) {
        // load A (query) 64x32, transposed into k-pair-major packs
        #pragma unroll
        for (int p = 0; p < 2; ++p) {
            float4 v = *(const float4*)(Qb + (size_t)(qq + p*32)*Dn + kc + kk);
            *(float2*)&As2[k2s  ][qq + p*32] = make_float2(v.x, v.y);
            *(float2*)&As2[k2s+1][qq + p*32] = make_float2(v.z, v.w);
        }
        // load B (in_memory rows) 128x32
        #pragma unroll
        for (int p = 0; p < 4; ++p) {
            float4 v = *(const float4*)(Xb + (size_t)(qq + p*32)*Dn + kc + kk);
            *(float2*)&Bs2[k2s  ][qq + p*32] = make_float2(v.x, v.y);
            *(float2*)&Bs2[k2s+1][qq + p*32] = make_float2(v.z, v.w);
        }
        __syncthreads();

        #pragma unroll
        for (int k2 = 0; k2 < 16; ++k2) {
            ull a2[8], b2[4];
            ulonglong2 t;
            t = *(const ulonglong2*)&As2[k2][ty*8+0]; a2[0]=t.x; a2[1]=t.y;
            t = *(const ulonglong2*)&As2[k2][ty*8+2]; a2[2]=t.x; a2[3]=t.y;
            t = *(const ulonglong2*)&As2[k2][ty*8+4]; a2[4]=t.x; a2[5]=t.y;
            t = *(const ulonglong2*)&As2[k2][ty*8+6]; a2[6]=t.x; a2[7]=t.y;
            t = *(const ulonglong2*)&Bs2[k2][tx*4+0]; b2[0]=t.x; b2[1]=t.y;
            t = *(const ulonglong2*)&Bs2[k2][tx*4+2]; b2[2]=t.x; b2[3]=t.y;
            #pragma unroll
            for (int i = 0; i < 8; ++i)
                #pragma unroll
                for (int j = 0; j < 4; ++j)
                    FMA2(acc[i][j], a2[i], b2[j]);
        }

        // fused in_mem base: sum_f wS[m][f] * x[m,f,kc+rk]  (reads smem tile)
        {
            const float* rowp = (const float*)&Bs2[rk2][rm*16];
            float s = 0.f;
            #pragma unroll
            for (int f = 0; f < Fn; ++f)
                s += wS[rm][f] * rowp[f*2 + rhalf];
            inout[kc] = s;
        }
        __syncthreads();
    }

    // epilogue: combine pair-lanes, apply masks, max over F (4 regs x 4 lanes)
    #pragma unroll
    for (int i = 0; i < 8; ++i) {
        const int q = ty*8 + i;
        const float qm = qmS[q];
        float mx = -3e38f;
        #pragma unroll
        for (int j = 0; j < 4; ++j) {
            const int r = tx*4 + j;
            const unsigned lo = (unsigned)(acc[i][j] & 0xffffffffULL);
            const unsigned hi = (unsigned)(acc[i][j] >> 32);
            float s = __uint_as_float(lo) + __uint_as_float(hi);
            const float cm = cmS[r];
            s = cm*s - (1.f - cm)*INF_;
            s = qm*s - (1.f - qm)*INF_;
            mx = fmaxf(mx, s);
        }
        mx = fmaxf(mx, __shfl_xor_sync(0xffffffffu, mx, 1));
        mx = fmaxf(mx, __shfl_xor_sync(0xffffffffu, mx, 2));
        if ((tx & 3) == 0)
            g_att[((size_t)(b*Qn + q))*Mn + m0 + (tx >> 2)] = mx;
    }
}

// =====================================================================
// K2: out_mem = sum_f out_memory   (in_mem now produced by K1)
// one block per (b,m); 128 threads, one float4 of D each
// =====================================================================
__global__ void k2_outsum(const float* __restrict__ outmem,
                          float* __restrict__ dout)
{
    const int bm = blockIdx.x;                     // 0..B*M-1
    const float4* Y = (const float4*)(outmem + (size_t)bm*Fn*Dn);
    const int d4 = threadIdx.x;                    // 0..127
    float4 ao = make_float4(0.f,0.f,0.f,0.f);
    #pragma unroll
    for (int f = 0; f < Fn; ++f) {
        const float4 y = Y[f*128 + d4];
        ao.x += y.x; ao.y += y.y; ao.z += y.z; ao.w += y.w;
    }
    ((float4*)(dout + OFF_OM))[(size_t)bm*128 + d4] = ao;
}

// =====================================================================
// K3a: softmax stats over M per (b,q)
// =====================================================================
__global__ void k3a_stats()
{
    const int bq  = blockIdx.x;                    // 0..B*Q-1
    const int tid = threadIdx.x;                   // 128
    const float4 v = ((const float4*)(g_att + (size_t)bq*Mn))[tid];
    float mx = fmaxf(fmaxf(v.x, v.y), fmaxf(v.z, v.w));
    #pragma unroll
    for (int o = 16; o > 0; o >>= 1) mx = fmaxf(mx, __shfl_xor_sync(~0u, mx, o));
    __shared__ float sm[4], ss[4];
    if ((tid & 31) == 0) sm[tid >> 5] = mx;
    __syncthreads();
    mx = fmaxf(fmaxf(sm[0], sm[1]), fmaxf(sm[2], sm[3]));
    float s = __expf(v.x-mx) + __expf(v.y-mx) + __expf(v.z-mx) + __expf(v.w-mx);
    #pragma unroll
    for (int o = 16; o > 0; o >>= 1) s += __shfl_xor_sync(~0u, s, o);
    if ((tid & 31) == 0) ss[tid >> 5] = s;
    __syncthreads();
    if (tid == 0) { g_rmax[bq] = mx; g_rsum[bq] = ss[0]+ss[1]+ss[2]+ss[3]; }
}

// =====================================================================
// K3b: new_query = query + softmax_M(att) @ out_mem
// block: (32 q x 64 d) tile; 256 blocks -> 2 CTAs/SM (was 128 blocks, occ 12.5%)
// =====================================================================
__global__ __launch_bounds__(256, 2) void k3b_newq(const float* __restrict__ query,
                                                   float* __restrict__ dout)
{
    const int b  = blockIdx.z;
    const int q0 = blockIdx.y * 32;
    const int d0 = blockIdx.x * 64;
    __shared__ __align__(16) float ps[32][68];     // [q][m_local]
    __shared__ __align__(16) float om[64][68];     // [m_local][d_local]
    const int tid = threadIdx.x;
    const int tx  = tid & 15, ty = tid >> 4;       // ty: 2 q each
    const int lq  = tid >> 3, sm8 = (tid & 7) * 8; // ps loader
    const int lm  = tid >> 2, su4 = tid & 3;       // om loader

    const float rmL   = g_rmax[b*Qn + q0 + lq];
    const float rinvL = 1.f / g_rsum[b*Qn + q0 + lq];
    const float* om_g = dout + OFF_OM + (size_t)b*Mn*Dn;
    const float* attq = g_att + ((size_t)(b*Qn + q0 + lq))*Mn;

    float c[2][4];
    #pragma unroll
    for (int i = 0; i < 2; ++i)
        #pragma unroll
        for (int j = 0; j < 4; ++j) c[i][j] = 0.f;

    for (int mc = 0; mc < Mn; mc += 64) {
        #pragma unroll
        for (int p = 0; p < 2; ++p) {
            float4 v = *(const float4*)(attq + mc + sm8 + p*4);
            ps[lq][sm8+p*4+0] = __expf(v.x - rmL)*rinvL;
            ps[lq][sm8+p*4+1] = __expf(v.y - rmL)*rinvL;
            ps[lq][sm8+p*4+2] = __expf(v.z - rmL)*rinvL;
            ps[lq][sm8+p*4+3] = __expf(v.w - rmL)*rinvL;
        }
        #pragma unroll
        for (int p = 0; p < 4; ++p) {
            const int ml = su4*4 + p*16;
            float4 u = *(const float4*)(om_g + (size_t)(mc + lm)*Dn + d0 + ml);
            om[lm][ml+0] = u.x; om[lm][ml+1] = u.y; om[lm][ml+2] = u.z; om[lm][ml+3] = u.w;
        }
        __syncthreads();
        #pragma unroll
        for (int k = 0; k < 64; ++k) {
            const float a0 = ps[ty*2+0][k], a1 = ps[ty*2+1][k];
            const float4 bv = *(const float4*)&om[k][tx*4];
            c[0][0]+=a0*bv.x; c[0][1]+=a0*bv.y; c[0][2]+=a0*bv.z; c[0][3]+=a0*bv.w;
            c[1][0]+=a1*bv.x; c[1][1]+=a1*bv.y; c[1][2]+=a1*bv.z; c[1][3]+=a1*bv.w;
        }
        __syncthreads();
    }
    #pragma unroll
    for (int i = 0; i < 2; ++i) {
        const int q = q0 + ty*2 + i;
        const float4 qv = *(const float4*)(query + ((size_t)(b*Qn + q))*Dn + d0 + tx*4);
        float4 o = make_float4(qv.x + c[i][0], qv.y + c[i][1],
                               qv.z + c[i][2], qv.w + c[i][3]);
        *(float4*)(dout + OFF_NQ + ((size_t)(b*Qn + q))*Dn + d0 + tx*4) = o;
    }
}

// =====================================================================
// K4a: softmax stats over Q (axis=1) per (b,m)
// grid = Bn*4 blocks of 128 threads (m-chunks of 128)
// =====================================================================
__global__ void k4a_stats()
{
    const int b = blockIdx.x >> 2;
    const int m = (blockIdx.x & 3) * 128 + threadIdx.x;
    const float* base = g_att + (size_t)b*Qn*Mn + m;
    float mx = -3e38f;
    #pragma unroll 8
    for (int q = 0; q < Qn; ++q) mx = fmaxf(mx, base[q*Mn]);
    float s = 0.f;
    #pragma unroll 8
    for (int q = 0; q < Qn; ++q) s += __expf(base[q*Mn] - mx);
    g_cmax[b*Mn + m] = mx;
    g_csum[b*Mn + m] = s;
}

// =====================================================================
// K4b: in_mem += softmax_Q(att)^T @ new_query   (K = 64 q)
// block: (64 m x 64 d) tile
// =====================================================================
__global__ __launch_bounds__(256) void k4b_inmem(float* __restrict__ dout)
{
    const int b  = blockIdx.z;
    const int m0 = blockIdx.y * 64;
    const int d0 = blockIdx.x * 64;
    __shared__ __align__(16) float pt[64][68];     // [q][m_local]
    __shared__ __align__(16) float nq[64][68];     // [q][d_local]
    __shared__ float cmx[64], cs[64];
    const int tid = threadIdx.x;
    const int tx  = tid & 15, ty = tid >> 4;
    const int lq  = tid >> 2, sub = tid & 3;

    if (tid < 64) {
        cmx[tid] = g_cmax[b*Mn + m0 + tid];
        cs[tid]  = 1.f / g_csum[b*Mn + m0 + tid];
    }
    __syncthreads();

    #pragma unroll
    for (int p = 0; p < 4; ++p) {
        const int ml = sub*4 + p*16;
        float4 v = *(const float4*)(g_att + ((size_t)(b*Qn + lq))*Mn + m0 + ml);
        pt[lq][ml+0] = __expf(v.x - cmx[ml+0]) * cs[ml+0];
        pt[lq][ml+1] = __expf(v.y - cmx[ml+1]) * cs[ml+1];
        pt[lq][ml+2] = __expf(v.z - cmx[ml+2]) * cs[ml+2];
        pt[lq][ml+3] = __expf(v.w - cmx[ml+3]) * cs[ml+3];
        float4 u = *(const float4*)(dout + OFF_NQ + ((size_t)(b*Qn + lq))*Dn + d0 + ml);
        nq[lq][ml+0] = u.x; nq[lq][ml+1] = u.y; nq[lq][ml+2] = u.z; nq[lq][ml+3] = u.w;
    }
    __syncthreads();

    float c[4][4];
    #pragma unroll
    for (int i = 0; i < 4; ++i)
        #pragma unroll
        for (int j = 0; j < 4; ++j) c[i][j] = 0.f;

    #pragma unroll
    for (int k = 0; k < 64; ++k) {
        const float a0 = pt[k][ty*4+0], a1 = pt[k][ty*4+1];
        const float a2 = pt[k][ty*4+2], a3 = pt[k][ty*4+3];
        const float4 bv = *(const float4*)&nq[k][tx*4];
        c[0][0]+=a0*bv.x; c[0][1]+=a0*bv.y; c[0][2]+=a0*bv.z; c[0][3]+=a0*bv.w;
        c[1][0]+=a1*bv.x; c[1][1]+=a1*bv.y; c[1][2]+=a1*bv.z; c[1][3]+=a1*bv.w;
        c[2][0]+=a2*bv.x; c[2][1]+=a2*bv.y; c[2][2]+=a2*bv.z; c[2][3]+=a2*bv.w;
        c[3][0]+=a3*bv.x; c[3][1]+=a3*bv.y; c[3][2]+=a3*bv.z; c[3][3]+=a3*bv.w;
    }

    #pragma unroll
    for (int i = 0; i < 4; ++i) {
        const int m = m0 + ty*4 + i;
        float* p = dout + OFF_IN + ((size_t)(b*Mn + m))*Dn + d0 + tx*4;
        float4 v = *(const float4*)p;
        v.x += c[i][0]; v.y += c[i][1]; v.z += c[i][2]; v.w += c[i][3];
        *(float4*)p = v;
    }
}

// =====================================================================
extern "C" void kernel_launch(void* const* d_in, const int* in_sizes, int n_in,
                              void* d_out, int out_size)
{
    const float* query  = (const float*)d_in[0];
    const float* inmem  = (const float*)d_in[1];
    const float* outmem = (const float*)d_in[2];
    const float* cmask  = (const float*)d_in[3];
    const float* qmask  = (const float*)d_in[4];
    float* dout = (float*)d_out;
    (void)in_sizes; (void)n_in; (void)out_size;

    dim3 g1(Mn/8, Bn);
    k1_attention<<<g1, 256>>>(query, inmem, cmask, qmask, dout);
    k2_outsum<<<Bn*Mn, 128>>>(outmem, dout);
    k3a_stats<<<Bn*Qn, 128>>>();
    dim3 g3(Dn/64, Qn/32, Bn);
    k3b_newq<<<g3, 256>>>(query, dout);
    k4a_stats<<<Bn*4, 128>>>();
    dim3 g4(Dn/64, Mn/64, Bn);
    k4b_inmem<<<g4, 256>>>(dout);
}

// round 6
// speedup vs baseline: 1.1282x; 1.0746x over previous
#include <cuda_runtime.h>
#include <math.h>
#include <stdint.h>

#define Bn 16
#define Qn 64
#define Mn 512
#define Fn 16
#define Dn 512
#define INF_ 1e20f

// d_out layout: [new_query (B,Q,D)][in_mem (B,M,D)][out_mem (B,M,D)]
#define OFF_NQ 0
#define OFF_IN (Bn*Qn*Dn)                 // 524288
#define OFF_OM (OFF_IN + Bn*Mn*Dn)       // 4718592

typedef unsigned long long ull;

// ---------------- scratch (no allocations allowed) ----------------
__device__ float g_att[Bn*Qn*Mn];   // att_qm (B,Q,M)  2MB
__device__ float g_rmax[Bn*Qn];
__device__ float g_rsum[Bn*Qn];
__device__ float g_cmax[Bn*Mn];
__device__ float g_csum[Bn*Mn];

// packed fp32x2 FMA (PTX-only; doubles fp32 FMA rate on sm_103a)
#define FMA2(c, a, b) asm("fma.rn.f32x2 %0, %1, %2, %0;" : "+l"(c) : "l"(a), "l"(b))

__device__ __forceinline__ uint32_t s2u(const void* p) {
    uint32_t a;
    asm("{ .reg .u64 t; cvta.to.shared.u64 t, %1; cvt.u32.u64 %0, t; }" : "=r"(a) : "l"(p));
    return a;
}
__device__ __forceinline__ void cpa16(uint32_t dst, const float* src) {
    asm volatile("cp.async.cg.shared.global [%0], [%1], 16;" :: "r"(dst), "l"(src) : "memory");
}

// smem geometry (floats): rows padded to 36 (144B, 16B-aligned, stride=4 banks)
#define ROWP 36
#define A_BUF (64*ROWP)     // 2304 floats / buffer
#define B_BUF (128*ROWP)    // 4608 floats / buffer
#define NBUF 3
#define K1_SMEM ((NBUF*A_BUF + NBUF*B_BUF)*4)   // 82944 bytes

// =====================================================================
// K1: attention = query @ in_memory^T, masks, max over F -> g_att
//     fused: in_mem base = softmax_f(mask) . in_memory -> dout[OFF_IN]
// Block: 64 q x 128 rows (8 m x 16 f). 256 thr, 8x4 f32x2 acc.
// cp.async 3-stage pipeline over 16 k-chunks of 32.
// =====================================================================
__global__ __launch_bounds__(256, 2) void k1_attention(
    const float* __restrict__ query, const float* __restrict__ inmem,
    const float* __restrict__ cmask, const float* __restrict__ qmask,
    float* __restrict__ dout)
{
    extern __shared__ __align__(16) float dsm[];
    float* AsB = dsm;                       // [NBUF][64][ROWP]
    float* BsB = dsm + NBUF*A_BUF;          // [NBUF][128][ROWP]
    __shared__ float cmS[128];
    __shared__ float qmS[64];
    __shared__ float wS[8][16];

    const int b  = blockIdx.y;
    const int m0 = blockIdx.x * 8;
    const int r0 = m0 * 16;
    const int tid = threadIdx.x;
    const int tx  = tid & 31;
    const int ty  = tid >> 5;

    const float* Qb = query + (size_t)b * Qn * Dn;
    const float* Xb = inmem + ((size_t)b * (Mn*Fn) + r0) * Dn;
    const uint32_t as_u = s2u(AsB);
    const uint32_t bs_u = s2u(BsB);

    if (tid < 128) cmS[tid] = cmask[(size_t)(b*Mn + m0)*Fn + tid];
    if (tid < 64)  qmS[tid] = qmask[b*Qn + tid];

    // per-m softmax over F of mask values: warp w handles m0+w, lanes 0..15 = f
    {
        const int wm = ty, wf = tx;
        float mv = -3e38f, c = 0.f;
        if (wf < Fn) {
            c  = cmask[(size_t)(b*Mn + m0 + wm)*Fn + wf];
            mv = c - (1.f - c)*INF_;
        }
        float mx = mv;
        #pragma unroll
        for (int o = 8; o > 0; o >>= 1) mx = fmaxf(mx, __shfl_xor_sync(~0u, mx, o));
        mx = __shfl_sync(~0u, mx, 0, 16);
        float e = (wf < Fn) ? __expf(mv - mx) : 0.f;
        float s = e;
        #pragma unroll
        for (int o = 8; o > 0; o >>= 1) s += __shfl_xor_sync(~0u, s, o);
        s = __shfl_sync(~0u, s, 0, 16);
        if (wf < Fn) wS[wm][wf] = e / s;
    }

    ull acc[8][4];
    #pragma unroll
    for (int i = 0; i < 8; ++i)
        #pragma unroll
        for (int j = 0; j < 4; ++j) acc[i][j] = 0ULL;

    // cp.async issue: A = 512 x 16B (2/thread), B = 1024 x 16B (4/thread)
    const int ac0 = tid*2, bc0 = tid*4;

    // prologue: chunk 0 into buffer 0
    {
        #pragma unroll
        for (int p = 0; p < 2; ++p) {
            const int c = ac0 + p, row = c >> 3, col = (c & 7)*4;
            cpa16(as_u + (uint32_t)(row*ROWP + col)*4, Qb + (size_t)row*Dn + col);
        }
        #pragma unroll
        for (int p = 0; p < 4; ++p) {
            const int c = bc0 + p, row = c >> 3, col = (c & 7)*4;
            cpa16(bs_u + (uint32_t)(row*ROWP + col)*4, Xb + (size_t)row*Dn + col);
        }
        asm volatile("cp.async.commit_group;" ::: "memory");
    }

    for (int ic = 0; ic < 16; ++ic) {
        if (ic < 15) {
            const int kc = (ic + 1) * 32;
            const int nb = (ic + 1) % NBUF;
            #pragma unroll
            for (int p = 0; p < 2; ++p) {
                const int c = ac0 + p, row = c >> 3, col = (c & 7)*4;
                cpa16(as_u + (uint32_t)(nb*A_BUF + row*ROWP + col)*4,
                      Qb + (size_t)row*Dn + kc + col);
            }
            #pragma unroll
            for (int p = 0; p < 4; ++p) {
                const int c = bc0 + p, row = c >> 3, col = (c & 7)*4;
                cpa16(bs_u + (uint32_t)(nb*B_BUF + row*ROWP + col)*4,
                      Xb + (size_t)row*Dn + kc + col);
            }
            asm volatile("cp.async.commit_group;" ::: "memory");
            asm volatile("cp.async.wait_group 1;" ::: "memory");
        } else {
            asm volatile("cp.async.wait_group 0;" ::: "memory");
        }
        __syncthreads();

        const float* Asb = AsB + (ic % NBUF)*A_BUF;
        const float* Bsb = BsB + (ic % NBUF)*B_BUF;

        #pragma unroll
        for (int k2 = 0; k2 < 16; ++k2) {
            ull a2[8], b2[4];
            #pragma unroll
            for (int i = 0; i < 8; ++i)      // warp-uniform broadcast
                a2[i] = *(const ull*)(Asb + (ty*8 + i)*ROWP + 2*k2);
            #pragma unroll
            for (int j = 0; j < 4; ++j)      // r = tx + 32j, lane stride 4 banks
                b2[j] = *(const ull*)(Bsb + (tx + j*32)*ROWP + 2*k2);
            #pragma unroll
            for (int i = 0; i < 8; ++i)
                #pragma unroll
                for (int j = 0; j < 4; ++j)
                    FMA2(acc[i][j], a2[i], b2[j]);
        }

        // fused in_mem base: warp ty -> m0+ty, lane tx -> k within chunk
        {
            float s = 0.f;
            #pragma unroll
            for (int f = 0; f < Fn; ++f)
                s += wS[ty][f] * Bsb[(ty*16 + f)*ROWP + tx];
            dout[OFF_IN + ((size_t)(b*Mn + m0 + ty))*Dn + ic*32 + tx] = s;
        }
        __syncthreads();
    }

    // epilogue: combine pair lanes, masks, max over F (16-lane halves)
    #pragma unroll
    for (int i = 0; i < 8; ++i) {
        const int q  = ty*8 + i;
        const float qm = qmS[q];
        #pragma unroll
        for (int j = 0; j < 4; ++j) {
            const int r = tx + j*32;
            const unsigned lo = (unsigned)(acc[i][j] & 0xffffffffULL);
            const unsigned hi = (unsigned)(acc[i][j] >> 32);
            float s = __uint_as_float(lo) + __uint_as_float(hi);
            const float cm = cmS[r];
            s = cm*s - (1.f - cm)*INF_;
            s = qm*s - (1.f - qm)*INF_;
            s = fmaxf(s, __shfl_xor_sync(0xffffffffu, s, 1));
            s = fmaxf(s, __shfl_xor_sync(0xffffffffu, s, 2));
            s = fmaxf(s, __shfl_xor_sync(0xffffffffu, s, 4));
            s = fmaxf(s, __shfl_xor_sync(0xffffffffu, s, 8));
            if ((tx & 15) == 0)
                g_att[((size_t)(b*Qn + q))*Mn + m0 + (tx >> 4) + 2*j] = s;
        }
    }
}

// =====================================================================
// K2: out_mem = sum_f out_memory
// =====================================================================
__global__ void k2_outsum(const float* __restrict__ outmem, float* __restrict__ dout)
{
    const int bm = blockIdx.x;
    const float4* Y = (const float4*)(outmem + (size_t)bm*Fn*Dn);
    const int d4 = threadIdx.x;
    float4 ao = make_float4(0.f, 0.f, 0.f, 0.f);
    #pragma unroll
    for (int f = 0; f < Fn; ++f) {
        const float4 y = Y[f*128 + d4];
        ao.x += y.x; ao.y += y.y; ao.z += y.z; ao.w += y.w;
    }
    ((float4*)(dout + OFF_OM))[(size_t)bm*128 + d4] = ao;
}

// =====================================================================
// K3a: softmax stats over M per (b,q)
// =====================================================================
__global__ void k3a_stats()
{
    const int bq  = blockIdx.x;
    const int tid = threadIdx.x;                   // 128
    const float4 v = ((const float4*)(g_att + (size_t)bq*Mn))[tid];
    float mx = fmaxf(fmaxf(v.x, v.y), fmaxf(v.z, v.w));
    #pragma unroll
    for (int o = 16; o > 0; o >>= 1) mx = fmaxf(mx, __shfl_xor_sync(~0u, mx, o));
    __shared__ float sm[4], ss[4];
    if ((tid & 31) == 0) sm[tid >> 5] = mx;
    __syncthreads();
    mx = fmaxf(fmaxf(sm[0], sm[1]), fmaxf(sm[2], sm[3]));
    float s = __expf(v.x-mx) + __expf(v.y-mx) + __expf(v.z-mx) + __expf(v.w-mx);
    #pragma unroll
    for (int o = 16; o > 0; o >>= 1) s += __shfl_xor_sync(~0u, s, o);
    if ((tid & 31) == 0) ss[tid >> 5] = s;
    __syncthreads();
    if (tid == 0) { g_rmax[bq] = mx; g_rsum[bq] = ss[0]+ss[1]+ss[2]+ss[3]; }
}

// =====================================================================
// K3b: new_query = query + softmax_M(att) @ out_mem  (64q x 64d, 4x4/thread)
// =====================================================================
__global__ __launch_bounds__(256) void k3b_newq(const float* __restrict__ query,
                                                float* __restrict__ dout)
{
    const int b  = blockIdx.y;
    const int d0 = blockIdx.x * 64;
    __shared__ __align__(16) float ps[64][68];
    __shared__ __align__(16) float om[64][68];
    const int tid = threadIdx.x;
    const int tx  = tid & 15, ty = tid >> 4;
    const int lq  = tid >> 2, sub = tid & 3;

    const float rm   = g_rmax[b*Qn + lq];
    const float rinv = 1.f / g_rsum[b*Qn + lq];
    const float* om_g = dout + OFF_OM + (size_t)b*Mn*Dn;

    float c[4][4];
    #pragma unroll
    for (int i = 0; i < 4; ++i)
        #pragma unroll
        for (int j = 0; j < 4; ++j) c[i][j] = 0.f;

    for (int mc = 0; mc < Mn; mc += 64) {
        #pragma unroll
        for (int p = 0; p < 4; ++p) {
            const int ml = sub*4 + p*16;
            float4 v = *(const float4*)(g_att + ((size_t)(b*Qn + lq))*Mn + mc + ml);
            ps[lq][ml+0] = __expf(v.x - rm)*rinv;
            ps[lq][ml+1] = __expf(v.y - rm)*rinv;
            ps[lq][ml+2] = __expf(v.z - rm)*rinv;
            ps[lq][ml+3] = __expf(v.w - rm)*rinv;
            float4 u = *(const float4*)(om_g + (size_t)(mc + lq)*Dn + d0 + ml);
            om[lq][ml+0] = u.x; om[lq][ml+1] = u.y; om[lq][ml+2] = u.z; om[lq][ml+3] = u.w;
        }
        __syncthreads();
        #pragma unroll
        for (int k = 0; k < 64; ++k) {
            const float a0 = ps[ty*4+0][k], a1 = ps[ty*4+1][k];
            const float a2 = ps[ty*4+2][k], a3 = ps[ty*4+3][k];
            const float4 bv = *(const float4*)&om[k][tx*4];
            c[0][0]+=a0*bv.x; c[0][1]+=a0*bv.y; c[0][2]+=a0*bv.z; c[0][3]+=a0*bv.w;
            c[1][0]+=a1*bv.x; c[1][1]+=a1*bv.y; c[1][2]+=a1*bv.z; c[1][3]+=a1*bv.w;
            c[2][0]+=a2*bv.x; c[2][1]+=a2*bv.y; c[2][2]+=a2*bv.z; c[2][3]+=a2*bv.w;
            c[3][0]+=a3*bv.x; c[3][1]+=a3*bv.y; c[3][2]+=a3*bv.z; c[3][3]+=a3*bv.w;
        }
        __syncthreads();
    }
    #pragma unroll
    for (int i = 0; i < 4; ++i) {
        const int q = ty*4 + i;
        const float4 qv = *(const float4*)(query + ((size_t)(b*Qn + q))*Dn + d0 + tx*4);
        float4 o = make_float4(qv.x + c[i][0], qv.y + c[i][1],
                               qv.z + c[i][2], qv.w + c[i][3]);
        *(float4*)(dout + OFF_NQ + ((size_t)(b*Qn + q))*Dn + d0 + tx*4) = o;
    }
}

// =====================================================================
// K4a: softmax stats over Q per (b,m)
// =====================================================================
__global__ void k4a_stats()
{
    const int b = blockIdx.x >> 2;
    const int m = (blockIdx.x & 3) * 128 + threadIdx.x;
    const float* base = g_att + (size_t)b*Qn*Mn + m;
    float mx = -3e38f;
    #pragma unroll 8
    for (int q = 0; q < Qn; ++q) mx = fmaxf(mx, base[q*Mn]);
    float s = 0.f;
    #pragma unroll 8
    for (int q = 0; q < Qn; ++q) s += __expf(base[q*Mn] - mx);
    g_cmax[b*Mn + m] = mx;
    g_csum[b*Mn + m] = s;
}

// =====================================================================
// K4b: in_mem += softmax_Q(att)^T @ new_query
// =====================================================================
__global__ __launch_bounds__(256) void k4b_inmem(float* __restrict__ dout)
{
    const int b  = blockIdx.z;
    const int m0 = blockIdx.y * 64;
    const int d0 = blockIdx.x * 64;
    __shared__ __align__(16) float pt[64][68];
    __shared__ __align__(16) float nq[64][68];
    __shared__ float cmx[64], cs[64];
    const int tid = threadIdx.x;
    const int tx  = tid & 15, ty = tid >> 4;
    const int lq  = tid >> 2, sub = tid & 3;

    if (tid < 64) {
        cmx[tid] = g_cmax[b*Mn + m0 + tid];
        cs[tid]  = 1.f / g_csum[b*Mn + m0 + tid];
    }
    __syncthreads();

    #pragma unroll
    for (int p = 0; p < 4; ++p) {
        const int ml = sub*4 + p*16;
        float4 v = *(const float4*)(g_att + ((size_t)(b*Qn + lq))*Mn + m0 + ml);
        pt[lq][ml+0] = __expf(v.x - cmx[ml+0]) * cs[ml+0];
        pt[lq][ml+1] = __expf(v.y - cmx[ml+1]) * cs[ml+1];
        pt[lq][ml+2] = __expf(v.z - cmx[ml+2]) * cs[ml+2];
        pt[lq][ml+3] = __expf(v.w - cmx[ml+3]) * cs[ml+3];
        float4 u = *(const float4*)(dout + OFF_NQ + ((size_t)(b*Qn + lq))*Dn + d0 + ml);
        nq[lq][ml+0] = u.x; nq[lq][ml+1] = u.y; nq[lq][ml+2] = u.z; nq[lq][ml+3] = u.w;
    }
    __syncthreads();

    float c[4][4];
    #pragma unroll
    for (int i = 0; i < 4; ++i)
        #pragma unroll
        for (int j = 0; j < 4; ++j) c[i][j] = 0.f;

    #pragma unroll
    for (int k = 0; k < 64; ++k) {
        const float a0 = pt[k][ty*4+0], a1 = pt[k][ty*4+1];
        const float a2 = pt[k][ty*4+2], a3 = pt[k][ty*4+3];
        const float4 bv = *(const float4*)&nq[k][tx*4];
        c[0][0]+=a0*bv.x; c[0][1]+=a0*bv.y; c[0][2]+=a0*bv.z; c[0][3]+=a0*bv.w;
        c[1][0]+=a1*bv.x; c[1][1]+=a1*bv.y; c[1][2]+=a1*bv.z; c[1][3]+=a1*bv.w;
        c[2][0]+=a2*bv.x; c[2][1]+=a2*bv.y; c[2][2]+=a2*bv.z; c[2][3]+=a2*bv.w;
        c[3][0]+=a3*bv.x; c[3][1]+=a3*bv.y; c[3][2]+=a3*bv.z; c[3][3]+=a3*bv.w;
    }

    #pragma unroll
    for (int i = 0; i < 4; ++i) {
        const int m = m0 + ty*4 + i;
        float* p = dout + OFF_IN + ((size_t)(b*Mn + m))*Dn + d0 + tx*4;
        float4 v = *(const float4*)p;
        v.x += c[i][0]; v.y += c[i][1]; v.z += c[i][2]; v.w += c[i][3];
        *(float4*)p = v;
    }
}

// =====================================================================
extern "C" void kernel_launch(void* const* d_in, const int* in_sizes, int n_in,
                              void* d_out, int out_size)
{
    const float* query  = (const float*)d_in[0];
    const float* inmem  = (const float*)d_in[1];
    const float* outmem = (const float*)d_in[2];
    const float* cmask  = (const float*)d_in[3];
    const float* qmask  = (const float*)d_in[4];
    float* dout = (float*)d_out;
    (void)in_sizes; (void)n_in; (void)out_size;

    static int configured = 0;
    if (!configured) {
        cudaFuncSetAttribute(k1_attention, cudaFuncAttributeMaxDynamicSharedMemorySize, K1_SMEM);
        configured = 1;
    }

    dim3 g1(Mn/8, Bn);
    k1_attention<<<g1, 256, K1_SMEM>>>(query, inmem, cmask, qmask, dout);
    k2_outsum<<<Bn*Mn, 128>>>(outmem, dout);
    k3a_stats<<<Bn*Qn, 128>>>();
    dim3 g3(Dn/64, Bn);
    k3b_newq<<<g3, 256>>>(query, dout);
    k4a_stats<<<Bn*4, 128>>>();
    dim3 g4(Dn/64, Mn/64, Bn);
    k4b_inmem<<<g4, 256>>>(dout);
}